// round 1
// baseline (speedup 1.0000x reference)
#include <cuda_runtime.h>

// Problem constants (fixed shapes per reference)
#define NPIX      102400            // B*H*W = 4*160*160
#define HW        25600             // H*W
#define NV        1024
#define OUT_ELEMS (NV * 2 * 32 * 32)  // 2,097,152 floats

// Gaussian in "bin coordinates": (x - c_p)/sigma = (t - p)/0.8, t = (x+1)*16 - 0.5
// exponent(log2) coefficient: -0.5/(0.8^2) * log2(e)
#define CEXP  (-1.12710546f)

__device__ int g_sizes[NV];

// ---------------------------------------------------------------------------
// Kernel 1: zero output + segment-size counters
// ---------------------------------------------------------------------------
__global__ void zero_kernel(float4* __restrict__ out) {
    int i = blockIdx.x * blockDim.x + threadIdx.x;
    if (i < OUT_ELEMS / 4) out[i] = make_float4(0.f, 0.f, 0.f, 0.f);
    if (i < NV) g_sizes[i] = 0;
}

// ---------------------------------------------------------------------------
// Vector reduction helper: 4 consecutive f32 adds to global (no return)
// ---------------------------------------------------------------------------
__device__ __forceinline__ void red4(float* p, float a, float b, float c, float d) {
    asm volatile("red.global.add.v4.f32 [%0], {%1,%2,%3,%4};"
                 :: "l"(p), "f"(a), "f"(b), "f"(c), "f"(d) : "memory");
}

// ---------------------------------------------------------------------------
// Kernel 2: per-pixel windowed Parzen scatter
// ---------------------------------------------------------------------------
__global__ void __launch_bounds__(256)
hist_kernel(const int* __restrict__ seg,
            const int* __restrict__ byx,
            const float* __restrict__ grad,
            float* __restrict__ out) {
    int n = blockIdx.x * blockDim.x + threadIdx.x;
    if (n >= NPIX) return;

    int v = seg[n];
    atomicAdd(&g_sizes[v], 1);   // discarded return -> RED

    const float SCL = 2.0f / 160.0f;
    float x0 = (float)byx[NPIX + n]     * SCL - 1.0f;   // y coord
    float x1 = (float)byx[2 * NPIX + n] * SCL - 1.0f;   // x coord
    int   b  = n / HW;
    int   hw = n - b * HW;
    float x2 = grad[b * 2 * HW + hw];        // grad[b,0,h,w]
    float x3 = grad[b * 2 * HW + HW + hw];   // grad[b,1,h,w]

    // bin coordinates
    float t0 = (x0 + 1.f) * 16.f - 0.5f;
    float t1 = (x1 + 1.f) * 16.f - 0.5f;
    float t2 = (x2 + 1.f) * 16.f - 0.5f;
    float t3 = (x3 + 1.f) * 16.f - 0.5f;

    float* base0 = out + (size_t)v * 2048;

    // ---- pair 0: dims (0,1) — always in range ----
    {
        int lo0 = min(20, max(0, (int)floorf(t0) - 5));
        float w0[12];
#pragma unroll
        for (int k = 0; k < 12; k++) {
            float d = t0 - (float)(lo0 + k);
            w0[k] = exp2f(CEXP * d * d);
        }
        int qa1 = min(16, max(0, ((int)floorf(t1) - 5) & ~3));
        float w1[16];
#pragma unroll
        for (int k = 0; k < 16; k++) {
            float d = t1 - (float)(qa1 + k);
            w1[k] = exp2f(CEXP * d * d);
        }
#pragma unroll
        for (int p = 0; p < 12; p++) {
            float a = w0[p];
            float* row = base0 + (lo0 + p) * 32 + qa1;
            red4(row,      a * w1[0],  a * w1[1],  a * w1[2],  a * w1[3]);
            red4(row + 4,  a * w1[4],  a * w1[5],  a * w1[6],  a * w1[7]);
            red4(row + 8,  a * w1[8],  a * w1[9],  a * w1[10], a * w1[11]);
            red4(row + 12, a * w1[12], a * w1[13], a * w1[14], a * w1[15]);
        }
    }

    // ---- pair 1: dims (2,3) — grads can be far out of [-1,1] -> skip ----
    bool in2 = (t2 > -5.6f) && (t2 < 36.6f);
    bool in3 = (t3 > -5.6f) && (t3 < 36.6f);
    if (in2 && in3) {
        int lo2 = min(20, max(0, (int)floorf(t2) - 5));
        float w2[12];
#pragma unroll
        for (int k = 0; k < 12; k++) {
            float d = t2 - (float)(lo2 + k);
            w2[k] = exp2f(CEXP * d * d);
        }
        int qa3 = min(16, max(0, ((int)floorf(t3) - 5) & ~3));
        float w3[16];
#pragma unroll
        for (int k = 0; k < 16; k++) {
            float d = t3 - (float)(qa3 + k);
            w3[k] = exp2f(CEXP * d * d);
        }
        float* base1 = base0 + 1024;
#pragma unroll
        for (int p = 0; p < 12; p++) {
            float a = w2[p];
            float* row = base1 + (lo2 + p) * 32 + qa3;
            red4(row,      a * w3[0],  a * w3[1],  a * w3[2],  a * w3[3]);
            red4(row + 4,  a * w3[4],  a * w3[5],  a * w3[6],  a * w3[7]);
            red4(row + 8,  a * w3[8],  a * w3[9],  a * w3[10], a * w3[11]);
            red4(row + 12, a * w3[12], a * w3[13], a * w3[14], a * w3[15]);
        }
    }
}

// ---------------------------------------------------------------------------
// Kernel 3: normalize by segment size (den = sizes * (P/32)^2 = sizes)
// ---------------------------------------------------------------------------
__global__ void finalize_kernel(float4* __restrict__ out) {
    int i = blockIdx.x * blockDim.x + threadIdx.x;
    if (i >= OUT_ELEMS / 4) return;
    int sz = g_sizes[i >> 9];               // (i*4) >> 11
    float inv = (sz > 0) ? (1.0f / (float)sz) : 0.0f;
    float4 x = out[i];
    x.x *= inv; x.y *= inv; x.z *= inv; x.w *= inv;
    out[i] = x;
}

// ---------------------------------------------------------------------------
extern "C" void kernel_launch(void* const* d_in, const int* in_sizes, int n_in,
                              void* d_out, int out_size) {
    const int*   seg  = (const int*)d_in[0];
    const int*   byx  = (const int*)d_in[1];
    const float* grad = (const float*)d_in[2];
    float*       out  = (float*)d_out;

    // zero: OUT_ELEMS/4 = 524288 threads
    zero_kernel<<<OUT_ELEMS / 4 / 256, 256>>>((float4*)out);

    // main scatter: one thread per pixel
    hist_kernel<<<(NPIX + 255) / 256, 256>>>(seg, byx, grad, out);

    // normalize
    finalize_kernel<<<OUT_ELEMS / 4 / 256, 256>>>((float4*)out);
}

// round 2
// speedup vs baseline: 1.6252x; 1.6252x over previous
#include <cuda_runtime.h>

// Fixed problem shape
#define NPIX      102400            // B*H*W = 4*160*160
#define HW        25600             // H*W
#define NV        1024
#define OUT_ELEMS (NV * 2 * 32 * 32)

// Gaussian in bin coordinates: t = (x+1)*16 - 0.5, sigma_bins = 0.8
// log2-space coefficient: -0.5/(0.8^2) * log2(e)
#define CEXP  (-1.12710546f)

__device__ int g_sizes[NV];

// ---------------------------------------------------------------------------
// Kernel 1: zero output + segment-size counters
// ---------------------------------------------------------------------------
__global__ void zero_kernel(float4* __restrict__ out) {
    int i = blockIdx.x * blockDim.x + threadIdx.x;
    if (i < OUT_ELEMS / 4) out[i] = make_float4(0.f, 0.f, 0.f, 0.f);
    if (i < NV) g_sizes[i] = 0;
}

// ---------------------------------------------------------------------------
// Kernel 2: segment bincount
// ---------------------------------------------------------------------------
__global__ void count_kernel(const int* __restrict__ seg) {
    int n = blockIdx.x * blockDim.x + threadIdx.x;
    if (n < NPIX) atomicAdd(&g_sizes[seg[n]], 1);
}

// ---------------------------------------------------------------------------
// red.global.add.v4.f32 — 16B vector reduction, no return
// ---------------------------------------------------------------------------
__device__ __forceinline__ void red4(float* p, float a, float b, float c, float d) {
    asm volatile("red.global.add.v4.f32 [%0], {%1,%2,%3,%4};"
                 :: "l"(p), "f"(a), "f"(b), "f"(c), "f"(d) : "memory");
}

// ---------------------------------------------------------------------------
// Kernel 3: windowed Parzen scatter, normalization folded into p-weights.
// p-window: 8 bins (dropped weight <= exp(-12.5) ~ 3.7e-6)
// q-window: 12 bins, 4-aligned for red.v4 (covers floor-3..floor+4 always)
// ---------------------------------------------------------------------------
__global__ void __launch_bounds__(256)
hist_kernel(const int* __restrict__ seg,
            const int* __restrict__ byx,
            const float* __restrict__ grad,
            float* __restrict__ out) {
    int n = blockIdx.x * blockDim.x + threadIdx.x;
    if (n >= NPIX) return;

    int v = seg[n];
    float inv = 1.0f / (float)__ldg(&g_sizes[v]);   // den = sizes * (P/32)^2 = sizes

    // bin coordinates: t = (x+1)*16 - 0.5
    float t0 = (float)byx[NPIX + n]     * 0.2f - 0.5f;
    float t1 = (float)byx[2 * NPIX + n] * 0.2f - 0.5f;
    int   b  = n / HW;
    int   hw = n - b * HW;
    float t2 = grad[b * 2 * HW + hw]      * 16.f + 15.5f;
    float t3 = grad[b * 2 * HW + HW + hw] * 16.f + 15.5f;

    float* base0 = out + (size_t)v * 2048;

    // ---- pair 0: dims (0,1) — always in range ----
    {
        int lo0 = min(24, max(0, __float2int_rd(t0) - 3));
        float w0[8];
#pragma unroll
        for (int k = 0; k < 8; k++) {
            float d = t0 - (float)(lo0 + k);
            w0[k] = inv * exp2f(CEXP * d * d);
        }
        int qa1 = min(20, max(0, (__float2int_rd(t1) - 3) & ~3));
        float w1[12];
#pragma unroll
        for (int k = 0; k < 12; k++) {
            float d = t1 - (float)(qa1 + k);
            w1[k] = exp2f(CEXP * d * d);
        }
#pragma unroll
        for (int p = 0; p < 8; p++) {
            float a = w0[p];
            float* row = base0 + (lo0 + p) * 32 + qa1;
            red4(row,     a * w1[0], a * w1[1], a * w1[2],  a * w1[3]);
            red4(row + 4, a * w1[4], a * w1[5], a * w1[6],  a * w1[7]);
            red4(row + 8, a * w1[8], a * w1[9], a * w1[10], a * w1[11]);
        }
    }

    // ---- pair 1: dims (2,3) — grads can fall outside all bins -> skip ----
    if (t2 > -4.0f && t2 < 35.0f && t3 > -4.0f && t3 < 35.0f) {
        int lo2 = min(24, max(0, __float2int_rd(t2) - 3));
        float w2[8];
#pragma unroll
        for (int k = 0; k < 8; k++) {
            float d = t2 - (float)(lo2 + k);
            w2[k] = inv * exp2f(CEXP * d * d);
        }
        int qa3 = min(20, max(0, (__float2int_rd(t3) - 3) & ~3));
        float w3[12];
#pragma unroll
        for (int k = 0; k < 12; k++) {
            float d = t3 - (float)(qa3 + k);
            w3[k] = exp2f(CEXP * d * d);
        }
        float* base1 = base0 + 1024;
#pragma unroll
        for (int p = 0; p < 8; p++) {
            float a = w2[p];
            float* row = base1 + (lo2 + p) * 32 + qa3;
            red4(row,     a * w3[0], a * w3[1], a * w3[2],  a * w3[3]);
            red4(row + 4, a * w3[4], a * w3[5], a * w3[6],  a * w3[7]);
            red4(row + 8, a * w3[8], a * w3[9], a * w3[10], a * w3[11]);
        }
    }
}

// ---------------------------------------------------------------------------
extern "C" void kernel_launch(void* const* d_in, const int* in_sizes, int n_in,
                              void* d_out, int out_size) {
    const int*   seg  = (const int*)d_in[0];
    const int*   byx  = (const int*)d_in[1];
    const float* grad = (const float*)d_in[2];
    float*       out  = (float*)d_out;

    zero_kernel<<<OUT_ELEMS / 4 / 256, 256>>>((float4*)out);
    count_kernel<<<(NPIX + 255) / 256, 256>>>(seg);
    hist_kernel<<<(NPIX + 255) / 256, 256>>>(seg, byx, grad, out);
}

// round 3
// speedup vs baseline: 2.0482x; 1.2602x over previous
#include <cuda_runtime.h>

// Fixed problem shape
#define NPIX      102400            // B*H*W = 4*160*160
#define HW        25600             // H*W
#define NV        1024
#define OUT_ELEMS (NV * 2 * 32 * 32)

// Gaussian in bin coordinates: t = (x+1)*16 - 0.5, sigma_bins = 0.8
// log2-space coefficient: -0.5/(0.8^2) * log2(e)
#define CEXP   (-1.12710546f)
#define SKIPTH (2e-7f)

__device__ int g_sizes[NV];

// ---------------------------------------------------------------------------
// Kernel 1: zero output (grid-stride, 4 float4/thread) + segment-size counters
// ---------------------------------------------------------------------------
__global__ void zero_kernel(float4* __restrict__ out) {
    int t = blockIdx.x * 1024 + threadIdx.x;   // 512 blocks x 256 thr x 4
    float4 z = make_float4(0.f, 0.f, 0.f, 0.f);
#pragma unroll
    for (int k = 0; k < 4; k++) out[t + k * 256] = z;
    int i = blockIdx.x * blockDim.x + threadIdx.x;
    if (i < NV) g_sizes[i] = 0;
}

// ---------------------------------------------------------------------------
// Kernel 2: segment bincount
// ---------------------------------------------------------------------------
__global__ void count_kernel(const int* __restrict__ seg) {
    int n = blockIdx.x * blockDim.x + threadIdx.x;
    if (n < NPIX) atomicAdd(&g_sizes[seg[n]], 1);
}

// ---------------------------------------------------------------------------
// Predicated vector reduction: issue red.v4 only if gate > SKIPTH.
// Single predicated instruction — no divergent-branch overhead, and
// predicated-off lanes consume no LTS atomic throughput.
// ---------------------------------------------------------------------------
__device__ __forceinline__ void red4p(float gate, float* p,
                                      float a, float b, float c, float d) {
    asm volatile(
        "{\n\t"
        ".reg .pred pg;\n\t"
        "setp.gt.f32 pg, %0, %1;\n\t"
        "@pg red.global.add.v4.f32 [%2], {%3,%4,%5,%6};\n\t"
        "}"
        :: "f"(gate), "f"(SKIPTH), "l"(p), "f"(a), "f"(b), "f"(c), "f"(d)
        : "memory");
}

// ---------------------------------------------------------------------------
// Kernel 3: windowed Parzen scatter, normalization folded in.
// p-window: 7 bins centered on round(t)  (dropped weight <= exp(-9.57) ~ 7e-5)
// q-window: 12 bins, 4-aligned           (dropped weight <= exp(-12.5) ~ 3.7e-6)
// Corner chunks with product weight < 2e-7 are predicated off.
// ---------------------------------------------------------------------------
__global__ void __launch_bounds__(256)
hist_kernel(const int* __restrict__ seg,
            const int* __restrict__ byx,
            const float* __restrict__ grad,
            float* __restrict__ out) {
    int n = blockIdx.x * blockDim.x + threadIdx.x;
    if (n >= NPIX) return;

    int v = seg[n];
    float inv = 1.0f / (float)__ldg(&g_sizes[v]);   // den = sizes * (P/32)^2 = sizes

    // bin coordinates: t = (x+1)*16 - 0.5
    float t0 = (float)byx[NPIX + n]     * 0.2f - 0.5f;
    float t1 = (float)byx[2 * NPIX + n] * 0.2f - 0.5f;
    int   b  = n / HW;
    int   hw = n - b * HW;
    float t2 = grad[b * 2 * HW + hw]      * 16.f + 15.5f;
    float t3 = grad[b * 2 * HW + HW + hw] * 16.f + 15.5f;

    float* base0 = out + (size_t)v * 2048;

    // ---- pair 0: dims (0,1) — always in range ----
    {
        int lo0 = min(25, max(0, __float2int_rn(t0) - 3));
        float w0[7];                      // raw p-weights
#pragma unroll
        for (int k = 0; k < 7; k++) {
            float d = t0 - (float)(lo0 + k);
            w0[k] = exp2f(CEXP * d * d);
        }
        int qa1 = min(20, max(0, (__float2int_rd(t1) - 3) & ~3));
        float w1[12];                     // raw q-weights
#pragma unroll
        for (int k = 0; k < 12; k++) {
            float d = t1 - (float)(qa1 + k);
            w1[k] = exp2f(CEXP * d * d);
        }
        float m0 = fmaxf(fmaxf(w1[0], w1[1]),  fmaxf(w1[2],  w1[3]));
        float m1 = fmaxf(fmaxf(w1[4], w1[5]),  fmaxf(w1[6],  w1[7]));
        float m2 = fmaxf(fmaxf(w1[8], w1[9]),  fmaxf(w1[10], w1[11]));
#pragma unroll
        for (int p = 0; p < 7; p++) {
            float wr = w0[p];
            float a  = wr * inv;
            float* row = base0 + (lo0 + p) * 32 + qa1;
            red4p(wr * m0, row,     a * w1[0], a * w1[1], a * w1[2],  a * w1[3]);
            red4p(wr * m1, row + 4, a * w1[4], a * w1[5], a * w1[6],  a * w1[7]);
            red4p(wr * m2, row + 8, a * w1[8], a * w1[9], a * w1[10], a * w1[11]);
        }
    }

    // ---- pair 1: dims (2,3) — grads can fall outside all bins -> skip ----
    if (t2 > -4.0f && t2 < 35.0f && t3 > -4.0f && t3 < 35.0f) {
        int lo2 = min(25, max(0, __float2int_rn(t2) - 3));
        float w2[7];
#pragma unroll
        for (int k = 0; k < 7; k++) {
            float d = t2 - (float)(lo2 + k);
            w2[k] = exp2f(CEXP * d * d);
        }
        int qa3 = min(20, max(0, (__float2int_rd(t3) - 3) & ~3));
        float w3[12];
#pragma unroll
        for (int k = 0; k < 12; k++) {
            float d = t3 - (float)(qa3 + k);
            w3[k] = exp2f(CEXP * d * d);
        }
        float m0 = fmaxf(fmaxf(w3[0], w3[1]),  fmaxf(w3[2],  w3[3]));
        float m1 = fmaxf(fmaxf(w3[4], w3[5]),  fmaxf(w3[6],  w3[7]));
        float m2 = fmaxf(fmaxf(w3[8], w3[9]),  fmaxf(w3[10], w3[11]));
        float* base1 = base0 + 1024;
#pragma unroll
        for (int p = 0; p < 7; p++) {
            float wr = w2[p];
            float a  = wr * inv;
            float* row = base1 + (lo2 + p) * 32 + qa3;
            red4p(wr * m0, row,     a * w3[0], a * w3[1], a * w3[2],  a * w3[3]);
            red4p(wr * m1, row + 4, a * w3[4], a * w3[5], a * w3[6],  a * w3[7]);
            red4p(wr * m2, row + 8, a * w3[8], a * w3[9], a * w3[10], a * w3[11]);
        }
    }
}

// ---------------------------------------------------------------------------
extern "C" void kernel_launch(void* const* d_in, const int* in_sizes, int n_in,
                              void* d_out, int out_size) {
    const int*   seg  = (const int*)d_in[0];
    const int*   byx  = (const int*)d_in[1];
    const float* grad = (const float*)d_in[2];
    float*       out  = (float*)d_out;

    zero_kernel<<<512, 256>>>((float4*)out);
    count_kernel<<<(NPIX + 255) / 256, 256>>>(seg);
    hist_kernel<<<(NPIX + 255) / 256, 256>>>(seg, byx, grad, out);
}

// round 4
// speedup vs baseline: 2.3573x; 1.1509x over previous
#include <cuda_runtime.h>

// Fixed problem shape
#define NPIX      102400            // B*H*W = 4*160*160
#define HW        25600             // H*W
#define NV        1024
#define OUT_ELEMS (NV * 2 * 32 * 32)

// Gaussian in bin coordinates: t = (x+1)*16 - 0.5, sigma_bins = 0.8
// log2-space coefficient: -0.5/(0.8^2) * log2(e)
#define CEXP   (-1.12710546f)
#define SKIPTH (5e-6f)

__device__ int g_sizes[NV];

// ---------------------------------------------------------------------------
// Kernel 1: zero output + segment bincount (independent work, fused)
// 512 blocks x 256 threads. Each thread: 4 float4 zeros + 1 hist count bucket
// range (NPIX/131072 < 1 -> grid-stride with 1 element some threads idle ok).
// ---------------------------------------------------------------------------
__global__ void init_kernel(float4* __restrict__ out, const int* __restrict__ seg) {
    int tid = blockIdx.x * blockDim.x + threadIdx.x;   // 0..131071
    int t4  = blockIdx.x * 1024 + threadIdx.x;
    float4 z = make_float4(0.f, 0.f, 0.f, 0.f);
#pragma unroll
    for (int k = 0; k < 4; k++) out[t4 + k * 256] = z;
    if (tid < NV) g_sizes[tid] = 0;
    __threadfence();   // make the zeroed counters visible before counting
    __syncthreads();
    if (tid < NPIX) atomicAdd(&g_sizes[seg[tid]], 1);
}

// ---------------------------------------------------------------------------
// Predicated vector reduction: issue red.v4 only if gate > SKIPTH.
// ---------------------------------------------------------------------------
__device__ __forceinline__ void red4p(float gate, float* p,
                                      float a, float b, float c, float d) {
    asm volatile(
        "{\n\t"
        ".reg .pred pg;\n\t"
        "setp.gt.f32 pg, %0, %1;\n\t"
        "@pg red.global.add.v4.f32 [%2], {%3,%4,%5,%6};\n\t"
        "}"
        :: "f"(gate), "f"(SKIPTH), "l"(p), "f"(a), "f"(b), "f"(c), "f"(d)
        : "memory");
}

// ---------------------------------------------------------------------------
// Kernel 2: windowed Parzen scatter, normalization folded in.
// p-window: 6 bins (floor-2..floor+3; dropped tail fraction ~2e-4)
// q-window: 12 bins, 4-aligned; corner chunks with product < 5e-6 predicated off
// ---------------------------------------------------------------------------
__global__ void __launch_bounds__(256)
hist_kernel(const int* __restrict__ seg,
            const int* __restrict__ byx,
            const float* __restrict__ grad,
            float* __restrict__ out) {
    int n = blockIdx.x * blockDim.x + threadIdx.x;
    if (n >= NPIX) return;

    int v = seg[n];
    float inv = 1.0f / (float)__ldg(&g_sizes[v]);   // den = sizes * (P/32)^2 = sizes

    // bin coordinates: t = (x+1)*16 - 0.5
    float t0 = (float)byx[NPIX + n]     * 0.2f - 0.5f;
    float t1 = (float)byx[2 * NPIX + n] * 0.2f - 0.5f;
    int   b  = n / HW;
    int   hw = n - b * HW;
    float t2 = grad[b * 2 * HW + hw]      * 16.f + 15.5f;
    float t3 = grad[b * 2 * HW + HW + hw] * 16.f + 15.5f;

    float* base0 = out + (size_t)v * 2048;

    // ---- pair 0: dims (0,1) — always in range ----
    {
        int lo0 = min(26, max(0, __float2int_rd(t0) - 2));
        float w0[6];
#pragma unroll
        for (int k = 0; k < 6; k++) {
            float d = t0 - (float)(lo0 + k);
            w0[k] = exp2f(CEXP * d * d);
        }
        int qa1 = min(20, max(0, (__float2int_rd(t1) - 3) & ~3));
        float w1[12];
#pragma unroll
        for (int k = 0; k < 12; k++) {
            float d = t1 - (float)(qa1 + k);
            w1[k] = exp2f(CEXP * d * d);
        }
        float m0 = fmaxf(fmaxf(w1[0], w1[1]),  fmaxf(w1[2],  w1[3]));
        float m1 = fmaxf(fmaxf(w1[4], w1[5]),  fmaxf(w1[6],  w1[7]));
        float m2 = fmaxf(fmaxf(w1[8], w1[9]),  fmaxf(w1[10], w1[11]));
#pragma unroll
        for (int p = 0; p < 6; p++) {
            float wr = w0[p];
            float a  = wr * inv;
            float* row = base0 + (lo0 + p) * 32 + qa1;
            red4p(wr * m0, row,     a * w1[0], a * w1[1], a * w1[2],  a * w1[3]);
            red4p(wr * m1, row + 4, a * w1[4], a * w1[5], a * w1[6],  a * w1[7]);
            red4p(wr * m2, row + 8, a * w1[8], a * w1[9], a * w1[10], a * w1[11]);
        }
    }

    // ---- pair 1: dims (2,3) — grads can fall outside all bins -> skip ----
    if (t2 > -4.0f && t2 < 35.0f && t3 > -4.0f && t3 < 35.0f) {
        int lo2 = min(26, max(0, __float2int_rd(t2) - 2));
        float w2[6];
#pragma unroll
        for (int k = 0; k < 6; k++) {
            float d = t2 - (float)(lo2 + k);
            w2[k] = exp2f(CEXP * d * d);
        }
        int qa3 = min(20, max(0, (__float2int_rd(t3) - 3) & ~3));
        float w3[12];
#pragma unroll
        for (int k = 0; k < 12; k++) {
            float d = t3 - (float)(qa3 + k);
            w3[k] = exp2f(CEXP * d * d);
        }
        float m0 = fmaxf(fmaxf(w3[0], w3[1]),  fmaxf(w3[2],  w3[3]));
        float m1 = fmaxf(fmaxf(w3[4], w3[5]),  fmaxf(w3[6],  w3[7]));
        float m2 = fmaxf(fmaxf(w3[8], w3[9]),  fmaxf(w3[10], w3[11]));
        float* base1 = base0 + 1024;
#pragma unroll
        for (int p = 0; p < 6; p++) {
            float wr = w2[p];
            float a  = wr * inv;
            float* row = base1 + (lo2 + p) * 32 + qa3;
            red4p(wr * m0, row,     a * w3[0], a * w3[1], a * w3[2],  a * w3[3]);
            red4p(wr * m1, row + 4, a * w3[4], a * w3[5], a * w3[6],  a * w3[7]);
            red4p(wr * m2, row + 8, a * w3[8], a * w3[9], a * w3[10], a * w3[11]);
        }
    }
}

// ---------------------------------------------------------------------------
extern "C" void kernel_launch(void* const* d_in, const int* in_sizes, int n_in,
                              void* d_out, int out_size) {
    const int*   seg  = (const int*)d_in[0];
    const int*   byx  = (const int*)d_in[1];
    const float* grad = (const float*)d_in[2];
    float*       out  = (float*)d_out;

    init_kernel<<<512, 256>>>((float4*)out, seg);
    hist_kernel<<<(NPIX + 255) / 256, 256>>>(seg, byx, grad, out);
}